// round 4
// baseline (speedup 1.0000x reference)
#include <cuda_runtime.h>
#include <cuda_bf16.h>

#define B_ 4
#define S_ 512
#define D_ 256
#define U_ 128

// scratch for projections (allocation-free rule: device globals)
__device__ float g_Q[B_ * S_ * U_];
__device__ float g_V[B_ * S_ * U_];

__device__ __forceinline__ float tanh_fast(float x) {
    float y;
    asm("tanh.approx.f32 %0, %1;" : "=f"(y) : "f"(x));
    return y;
}

// ---------------------------------------------------------------------------
// Kernel 1: Q = values @ Wq, V = values @ Wv   (fused, both share values tile)
// grid = 2048/8 = 256 CTAs, 256 threads.
// threads 0..127 compute Q (u = t), threads 128..255 compute V (u = t-128).
// ---------------------------------------------------------------------------
__global__ void proj_kernel(const float* __restrict__ values,
                            const float* __restrict__ Wq,
                            const float* __restrict__ Wv) {
    __shared__ float sv[8][256];   // 8 rows of values
    const int t = threadIdx.x;
    const int rowbase = blockIdx.x * 8;

    // cooperative load of 8x256 floats (float4, coalesced)
    {
        const float4* src = (const float4*)(values + rowbase * D_);
        float4* dst = (float4*)&sv[0][0];
        #pragma unroll
        for (int i = 0; i < 2; i++) dst[t + i * 256] = src[t + i * 256];
    }
    __syncthreads();

    const int u = t & 127;
    const float* __restrict__ W = (t < 128) ? Wq : Wv;
    float* __restrict__ G = (t < 128) ? g_Q : g_V;

    float acc[8];
    #pragma unroll
    for (int r = 0; r < 8; r++) acc[r] = 0.f;

    #pragma unroll 4
    for (int k = 0; k < D_; k += 4) {
        const float w0 = W[(k + 0) * U_ + u];
        const float w1 = W[(k + 1) * U_ + u];
        const float w2 = W[(k + 2) * U_ + u];
        const float w3 = W[(k + 3) * U_ + u];
        #pragma unroll
        for (int r = 0; r < 8; r++) {
            float4 v = *(const float4*)&sv[r][k];   // warp-uniform broadcast
            acc[r] = fmaf(v.x, w0, acc[r]);
            acc[r] = fmaf(v.y, w1, acc[r]);
            acc[r] = fmaf(v.z, w2, acc[r]);
            acc[r] = fmaf(v.w, w3, acc[r]);
        }
    }

    #pragma unroll
    for (int r = 0; r < 8; r++)
        G[(rowbase + r) * U_ + u] = acc[r];
}

// ---------------------------------------------------------------------------
// Kernel 2: fused score + softmax + context.
// One CTA per balanced row pair (i0 = p, i1 = S-1-p) of one batch.
// grid = B * S/2 = 1024 CTAs, 256 threads.
// Dynamic smem layout:
//   [0)        vt   : 128 x 129 floats (v tile, pad-129 -> conflict-free)
//              red  : context partials alias vt region (8 KB)
//   [66048)    sc1  : 512 floats (scores row i1)
//   [68096)    sc0  : 512 floats (scores row i0)
//   [70144)    qw1  : 128 float2 (q1[u], Vw[u])
//   [71168)    qw0  : 128 float2
//   [72192)    redsc: 8 floats  (block reductions)
// ---------------------------------------------------------------------------
#define SMEM_BYTES 72320

__global__ void attn_kernel(const float* __restrict__ values,
                            const float* __restrict__ Vw,
                            float* __restrict__ out) {
    extern __shared__ char smem[];
    float*  vt    = (float*)smem;
    float*  red   = (float*)smem;              // aliases vt (used after scores)
    float*  sc1   = (float*)(smem + 66048);
    float*  sc0   = (float*)(smem + 68096);
    float2* qw1   = (float2*)(smem + 70144);
    float2* qw0   = (float2*)(smem + 71168);
    float*  redsc = (float*)(smem + 72192);

    const int t = threadIdx.x;
    const int b = blockIdx.x >> 8;
    const int p = blockIdx.x & 255;
    const int i0 = p;
    const int i1 = S_ - 1 - p;

    const float* __restrict__ gQb = g_Q + b * S_ * U_;
    const float* __restrict__ gVb = g_V + b * S_ * U_;
    const float* __restrict__ valb = values + b * S_ * D_;

    // init (q,Vw) packed rows
    if (t < 128) {
        qw1[t] = make_float2(gQb[i1 * U_ + t], Vw[t]);
    } else {
        const int u = t - 128;
        qw0[u] = make_float2(gQb[i0 * U_ + u], Vw[u]);
    }

    // ---- score phase: tiles of 128 j-columns ----
    for (int jt = 0; jt <= i1; jt += 128) {
        // load v tile [128 x 128] -> vt (pad 129), float4 gmem reads
        {
            const float4* src = (const float4*)(gVb + jt * U_);
            #pragma unroll
            for (int it = 0; it < 16; it++) {
                int idx4 = t + it * 256;            // 0..4095
                float4 v = src[idx4];
                int jr = idx4 >> 5;                 // /32 (32 float4 per row)
                int uu = (idx4 & 31) << 2;
                float* drow = &vt[jr * 129 + uu];
                drow[0] = v.x; drow[1] = v.y; drow[2] = v.z; drow[3] = v.w;
            }
        }
        __syncthreads();

        const int  jl   = t & 127;
        const bool row1 = (t < 128);
        const int  j    = jt + jl;
        const int  ilim = row1 ? i1 : i0;
        if (j <= ilim) {
            const float2* __restrict__ qw = row1 ? qw1 : qw0;
            const float*  __restrict__ vrow = &vt[jl * 129];
            float a0 = 0.f, a1 = 0.f, a2 = 0.f, a3 = 0.f;
            #pragma unroll 8
            for (int u = 0; u < U_; u += 4) {
                float2 c0 = qw[u + 0];
                float2 c1 = qw[u + 1];
                float2 c2 = qw[u + 2];
                float2 c3 = qw[u + 3];
                a0 = fmaf(tanh_fast(c0.x + vrow[u + 0]), c0.y, a0);
                a1 = fmaf(tanh_fast(c1.x + vrow[u + 1]), c1.y, a1);
                a2 = fmaf(tanh_fast(c2.x + vrow[u + 2]), c2.y, a2);
                a3 = fmaf(tanh_fast(c3.x + vrow[u + 3]), c3.y, a3);
            }
            (row1 ? sc1 : sc0)[j] = (a0 + a1) + (a2 + a3);
        }
        __syncthreads();
    }

    // ---- softmax (two independent halves, lockstep barriers) ----
    {
        const bool row1 = (t < 128);
        float* sc = row1 ? sc1 : sc0;
        const int L = row1 ? (i1 + 1) : (i0 + 1);
        const int hl = t & 127;
        const int wid = t >> 5;
        const int base = row1 ? 0 : 4;

        float m = -3.4e38f;
        for (int j = hl; j < L; j += 128) m = fmaxf(m, sc[j]);
        #pragma unroll
        for (int o = 16; o; o >>= 1) m = fmaxf(m, __shfl_xor_sync(0xffffffffu, m, o));
        if ((t & 31) == 0) redsc[wid] = m;
        __syncthreads();
        m = fmaxf(fmaxf(redsc[base], redsc[base + 1]),
                  fmaxf(redsc[base + 2], redsc[base + 3]));

        float s = 0.f;
        for (int j = hl; j < L; j += 128) {
            float e = __expf(sc[j] - m);
            sc[j] = e;
            s += e;
        }
        #pragma unroll
        for (int o = 16; o; o >>= 1) s += __shfl_xor_sync(0xffffffffu, s, o);
        __syncthreads();              // protect redsc reuse
        if ((t & 31) == 0) redsc[wid] = s;
        __syncthreads();
        s = redsc[base] + redsc[base + 1] + redsc[base + 2] + redsc[base + 3];
        const float inv = 1.0f / s;
        for (int j = hl; j < L; j += 128) sc[j] *= inv;
        __syncthreads();
    }

    // ---- context: out[i] = sum_j attn[j] * values[b,j,:] ----
    {
        const int jg = t >> 6;            // 0..3 : j residue class
        const int dg = (t & 63) << 2;     // float4 column base
        float4 A1 = make_float4(0.f, 0.f, 0.f, 0.f);
        float4 A0 = make_float4(0.f, 0.f, 0.f, 0.f);

        for (int j = jg; j <= i1; j += 4) {
            float4 v = *(const float4*)&valb[j * D_ + dg];
            float p1 = sc1[j];
            A1.x = fmaf(p1, v.x, A1.x);
            A1.y = fmaf(p1, v.y, A1.y);
            A1.z = fmaf(p1, v.z, A1.z);
            A1.w = fmaf(p1, v.w, A1.w);
            if (j <= i0) {
                float p0 = sc0[j];
                A0.x = fmaf(p0, v.x, A0.x);
                A0.y = fmaf(p0, v.y, A0.y);
                A0.z = fmaf(p0, v.z, A0.z);
                A0.w = fmaf(p0, v.w, A0.w);
            }
        }

        // partial reduction across the 4 j-classes via smem (aliases vt)
        float4* red4 = (float4*)red;
        red4[(jg * 2 + 0) * 64 + (t & 63)] = A1;
        red4[(jg * 2 + 1) * 64 + (t & 63)] = A0;
        __syncthreads();

        const bool row1 = (t < 128);
        const int  i    = row1 ? i1 : i0;
        const int  slot = row1 ? 0 : 1;
        const int  dl   = t & 127;
        float* ob = out + (b * S_ + i) * D_;
        #pragma unroll
        for (int h = 0; h < 2; h++) {
            int d = dl + h * 128;
            float o = red[(0 * 2 + slot) * 256 + d]
                    + red[(1 * 2 + slot) * 256 + d]
                    + red[(2 * 2 + slot) * 256 + d]
                    + red[(3 * 2 + slot) * 256 + d];
            ob[d] = o;
        }
    }
}

// ---------------------------------------------------------------------------
extern "C" void kernel_launch(void* const* d_in, const int* in_sizes, int n_in,
                              void* d_out, int out_size) {
    const float* values = (const float*)d_in[0];
    const float* Wq     = (const float*)d_in[1];
    const float* Wv     = (const float*)d_in[2];
    const float* Vw     = (const float*)d_in[3];
    float* out = (float*)d_out;

    cudaFuncSetAttribute(attn_kernel,
                         cudaFuncAttributeMaxDynamicSharedMemorySize, SMEM_BYTES);

    proj_kernel<<<(B_ * S_) / 8, 256>>>(values, Wq, Wv);
    attn_kernel<<<B_ * (S_ / 2), 256, SMEM_BYTES>>>(values, Vw, out);
}

// round 5
// speedup vs baseline: 1.1348x; 1.1348x over previous
#include <cuda_runtime.h>
#include <cuda_bf16.h>

#define B_ 4
#define S_ 512
#define D_ 256
#define U_ 128

// scratch for projections (allocation-free rule: device globals)
__device__ float g_Q[B_ * S_ * U_];
__device__ float g_V[B_ * S_ * U_];

__device__ __forceinline__ float tanh_fast(float x) {
    float y;
    asm("tanh.approx.f32 %0, %1;" : "=f"(y) : "f"(x));
    return y;
}

// ---------------------------------------------------------------------------
// Kernel 1: Q = values @ Wq, V = values @ Wv   (fused, both share values tile)
// ---------------------------------------------------------------------------
__global__ void proj_kernel(const float* __restrict__ values,
                            const float* __restrict__ Wq,
                            const float* __restrict__ Wv) {
    __shared__ float sv[8][256];   // 8 rows of values
    const int t = threadIdx.x;
    const int rowbase = blockIdx.x * 8;

    {
        const float4* src = (const float4*)(values + rowbase * D_);
        float4* dst = (float4*)&sv[0][0];
        #pragma unroll
        for (int i = 0; i < 2; i++) dst[t + i * 256] = src[t + i * 256];
    }
    __syncthreads();

    const int u = t & 127;
    const float* __restrict__ W = (t < 128) ? Wq : Wv;
    float* __restrict__ G = (t < 128) ? g_Q : g_V;

    float acc[8];
    #pragma unroll
    for (int r = 0; r < 8; r++) acc[r] = 0.f;

    #pragma unroll 4
    for (int k = 0; k < D_; k += 4) {
        const float w0 = W[(k + 0) * U_ + u];
        const float w1 = W[(k + 1) * U_ + u];
        const float w2 = W[(k + 2) * U_ + u];
        const float w3 = W[(k + 3) * U_ + u];
        #pragma unroll
        for (int r = 0; r < 8; r++) {
            float4 v = *(const float4*)&sv[r][k];
            acc[r] = fmaf(v.x, w0, acc[r]);
            acc[r] = fmaf(v.y, w1, acc[r]);
            acc[r] = fmaf(v.z, w2, acc[r]);
            acc[r] = fmaf(v.w, w3, acc[r]);
        }
    }

    #pragma unroll
    for (int r = 0; r < 8; r++)
        G[(rowbase + r) * U_ + u] = acc[r];
}

// ---------------------------------------------------------------------------
// Kernel 2: fused score + softmax + context.
// One CTA per balanced row pair (i0 = p, i1 = S-1-p). grid = B*S/2, 256 thr.
// Score tiling: 64 j-columns per tile; each (row, j) is computed by a LANE
// PAIR (two u-halves, combined with shfl_xor 1). Row = (t<128) stays
// warp-uniform so causal skipping saves real MUFU issue slots.
//
// smem layout (39488 B total -> 5 CTAs/SM):
//   [0)      vt   : 64 x 132 floats (v tile, pad-132 -> float4 conflict-free)
//            red  : context partials alias vt (8 KB)
//   [33792)  sc1  : 512 floats (exp scores row i1)
//   [35840)  sc0  : 512 floats (exp scores row i0)
//   [37888)  q1   : 128 floats
//   [38400)  q0   : 128 floats
//   [38912)  vw   : 128 floats
//   [39424)  redsc: 16 floats (block reductions + inv1/inv0 at [8],[9])
// ---------------------------------------------------------------------------
#define SMEM_BYTES 39488

__global__ void __launch_bounds__(256)
attn_kernel(const float* __restrict__ values,
            const float* __restrict__ Vw,
            float* __restrict__ out) {
    extern __shared__ char smem[];
    float*  vt    = (float*)smem;
    float*  red   = (float*)smem;              // aliases vt (after scores)
    float*  sc1   = (float*)(smem + 33792);
    float*  sc0   = (float*)(smem + 35840);
    float*  q1    = (float*)(smem + 37888);
    float*  q0    = (float*)(smem + 38400);
    float*  vw    = (float*)(smem + 38912);
    float*  redsc = (float*)(smem + 39424);

    const int t = threadIdx.x;
    const int b = blockIdx.x >> 8;
    const int p = blockIdx.x & 255;
    const int i0 = p;
    const int i1 = S_ - 1 - p;

    const float* __restrict__ gQb = g_Q + b * S_ * U_;
    const float* __restrict__ gVb = g_V + b * S_ * U_;
    const float* __restrict__ valb = values + b * S_ * D_;

    // init q rows + Vw copy
    if (t < 128) {
        q1[t] = gQb[i1 * U_ + t];
        vw[t] = Vw[t];
    } else {
        const int u = t - 128;
        q0[u] = gQb[i0 * U_ + u];
    }

    const bool row1 = (t < 128);
    const int  hl   = t & 127;
    const int  jl   = hl >> 1;     // 0..63
    const int  uh   = hl & 1;      // u-half
    const int  ilim = row1 ? i1 : i0;
    const float4* __restrict__ qv4 = (const float4*)(row1 ? q1 : q0) + uh * 16;
    const float4* __restrict__ w4  = (const float4*)vw + uh * 16;
    float* __restrict__ scrow = row1 ? sc1 : sc0;

    // ---- score phase: tiles of 64 j-columns ----
    for (int jt = 0; jt <= i1; jt += 64) {
        // load v tile [64 x 128] -> vt (pad 132), float4 everywhere
        {
            const float4* src = (const float4*)(gVb + jt * U_);
            float4* dst = (float4*)vt;
            #pragma unroll
            for (int it = 0; it < 8; it++) {
                int idx4 = t + it * 256;          // 0..2047
                float4 v = src[idx4];
                int jr = idx4 >> 5;               // row (32 float4 per row)
                int u4 = idx4 & 31;
                dst[jr * 33 + u4] = v;
            }
        }
        __syncthreads();

        const int j = jt + jl;
        const bool act = (j <= ilim);
        unsigned mask = __ballot_sync(0xffffffffu, act);
        if (act) {
            const float4* __restrict__ v4 =
                (const float4*)(vt + jl * 132) + uh * 16;
            float a0 = 0.f, a1 = 0.f, a2 = 0.f, a3 = 0.f;
            #pragma unroll 2
            for (int g = 0; g < 16; g++) {
                float4 v = v4[g];
                float4 q = qv4[g];
                float4 w = w4[g];
                a0 = fmaf(tanh_fast(q.x + v.x), w.x, a0);
                a1 = fmaf(tanh_fast(q.y + v.y), w.y, a1);
                a2 = fmaf(tanh_fast(q.z + v.z), w.z, a2);
                a3 = fmaf(tanh_fast(q.w + v.w), w.w, a3);
            }
            float a = (a0 + a1) + (a2 + a3);
            a += __shfl_xor_sync(mask, a, 1);     // combine u-halves
            if (uh == 0) scrow[j] = a;
        }
        __syncthreads();
    }

    // ---- softmax stats (exp in-place; 1/sum folded into context) ----
    {
        float* sc = scrow;
        const int L = ilim + 1;
        const int wid = t >> 5;
        const int base = row1 ? 0 : 4;

        float m = -3.4e38f;
        for (int j = hl; j < L; j += 128) m = fmaxf(m, sc[j]);
        #pragma unroll
        for (int o = 16; o; o >>= 1) m = fmaxf(m, __shfl_xor_sync(0xffffffffu, m, o));
        if ((t & 31) == 0) redsc[wid] = m;
        __syncthreads();
        m = fmaxf(fmaxf(redsc[base], redsc[base + 1]),
                  fmaxf(redsc[base + 2], redsc[base + 3]));

        float s = 0.f;
        for (int j = hl; j < L; j += 128) {
            float e = __expf(sc[j] - m);
            sc[j] = e;
            s += e;
        }
        #pragma unroll
        for (int o = 16; o; o >>= 1) s += __shfl_xor_sync(0xffffffffu, s, o);
        __syncthreads();              // protect redsc reuse
        if ((t & 31) == 0) redsc[wid] = s;
        __syncthreads();
        s = redsc[base] + redsc[base + 1] + redsc[base + 2] + redsc[base + 3];
        if (hl == 0) redsc[8 + (row1 ? 0 : 1)] = 1.0f / s;   // inv1 @8, inv0 @9
        __syncthreads();
    }

    // ---- context: out[i] = inv * sum_j exp_j * values[b,j,:] ----
    {
        const int jg = t >> 6;            // 0..3 : j residue class
        const int dg = (t & 63) << 2;     // float4 column base
        float4 A1 = make_float4(0.f, 0.f, 0.f, 0.f);
        float4 A0 = make_float4(0.f, 0.f, 0.f, 0.f);

        #pragma unroll 2
        for (int j = jg; j <= i1; j += 4) {
            float4 v = *(const float4*)&valb[j * D_ + dg];
            float p1 = sc1[j];
            A1.x = fmaf(p1, v.x, A1.x);
            A1.y = fmaf(p1, v.y, A1.y);
            A1.z = fmaf(p1, v.z, A1.z);
            A1.w = fmaf(p1, v.w, A1.w);
            if (j <= i0) {
                float p0 = sc0[j];
                A0.x = fmaf(p0, v.x, A0.x);
                A0.y = fmaf(p0, v.y, A0.y);
                A0.z = fmaf(p0, v.z, A0.z);
                A0.w = fmaf(p0, v.w, A0.w);
            }
        }

        // partial reduction across the 4 j-classes via smem (aliases vt)
        float4* red4 = (float4*)red;
        red4[(jg * 2 + 0) * 64 + (t & 63)] = A1;
        red4[(jg * 2 + 1) * 64 + (t & 63)] = A0;
        __syncthreads();

        const int  i    = row1 ? i1 : i0;
        const int  slot = row1 ? 0 : 1;
        const float inv = redsc[8 + slot];
        float* ob = out + (b * S_ + i) * D_;
        #pragma unroll
        for (int h = 0; h < 2; h++) {
            int d = hl + h * 128;
            float o = red[(0 * 2 + slot) * 256 + d]
                    + red[(1 * 2 + slot) * 256 + d]
                    + red[(2 * 2 + slot) * 256 + d]
                    + red[(3 * 2 + slot) * 256 + d];
            ob[d] = o * inv;
        }
    }
}

// ---------------------------------------------------------------------------
extern "C" void kernel_launch(void* const* d_in, const int* in_sizes, int n_in,
                              void* d_out, int out_size) {
    const float* values = (const float*)d_in[0];
    const float* Wq     = (const float*)d_in[1];
    const float* Wv     = (const float*)d_in[2];
    const float* Vw     = (const float*)d_in[3];
    float* out = (float*)d_out;

    cudaFuncSetAttribute(attn_kernel,
                         cudaFuncAttributeMaxDynamicSharedMemorySize, SMEM_BYTES);

    proj_kernel<<<(B_ * S_) / 8, 256>>>(values, Wq, Wv);
    attn_kernel<<<B_ * (S_ / 2), 256, SMEM_BYTES>>>(values, Vw, out);
}

// round 7
// speedup vs baseline: 1.3388x; 1.1798x over previous
#include <cuda_runtime.h>
#include <cuda_bf16.h>

#define B_ 4
#define S_ 512
#define D_ 256
#define U_ 128

// scratch for projections (allocation-free rule: device globals)
__device__ float g_Q[B_ * S_ * U_];
__device__ float g_V[B_ * S_ * U_];

__device__ __forceinline__ float tanh_fast(float x) {
    float y;
    asm("tanh.approx.f32 %0, %1;" : "=f"(y) : "f"(x));
    return y;
}

// ---------------------------------------------------------------------------
// Kernel 1: Q = values @ Wq, V = values @ Wv   (fused, both share values tile)
// ---------------------------------------------------------------------------
__global__ void proj_kernel(const float* __restrict__ values,
                            const float* __restrict__ Wq,
                            const float* __restrict__ Wv) {
    __shared__ float sv[8][256];   // 8 rows of values
    const int t = threadIdx.x;
    const int rowbase = blockIdx.x * 8;

    {
        const float4* src = (const float4*)(values + rowbase * D_);
        float4* dst = (float4*)&sv[0][0];
        #pragma unroll
        for (int i = 0; i < 2; i++) dst[t + i * 256] = src[t + i * 256];
    }
    __syncthreads();

    const int u = t & 127;
    const float* __restrict__ W = (t < 128) ? Wq : Wv;
    float* __restrict__ G = (t < 128) ? g_Q : g_V;

    float acc[8];
    #pragma unroll
    for (int r = 0; r < 8; r++) acc[r] = 0.f;

    #pragma unroll 4
    for (int k = 0; k < D_; k += 4) {
        const float w0 = W[(k + 0) * U_ + u];
        const float w1 = W[(k + 1) * U_ + u];
        const float w2 = W[(k + 2) * U_ + u];
        const float w3 = W[(k + 3) * U_ + u];
        #pragma unroll
        for (int r = 0; r < 8; r++) {
            float4 v = *(const float4*)&sv[r][k];
            acc[r] = fmaf(v.x, w0, acc[r]);
            acc[r] = fmaf(v.y, w1, acc[r]);
            acc[r] = fmaf(v.z, w2, acc[r]);
            acc[r] = fmaf(v.w, w3, acc[r]);
        }
    }

    #pragma unroll
    for (int r = 0; r < 8; r++)
        G[(rowbase + r) * U_ + u] = acc[r];
}

// ---------------------------------------------------------------------------
// Kernel 2: fused score + softmax + context.
// One CTA per balanced row pair (i0 = p, i1 = S-1-p). grid = B*S/2, 256 thr.
//
// Score phase: q1/q0/Vw chunks live in REGISTERS (8 u-values per thread,
// uc = t&15). Each thread computes BOTH rows for one j (jp = t>>4), so v is
// read from smem exactly once per (j,u): 2 LDS.128 per 16 tanh. Cross-u
// reduction = 16-lane shfl_xor tree. Causal skip for row0 is warp-uniform.
//
// smem layout (37952 B -> 5 CTAs/SM):
//   [0)      vt   : 64 x 132 floats (v tile, pad-132, float4 conflict-free)
//            red  : context partials alias vt (8 KB)
//   [33792)  sc1  : 512 floats (exp scores row i1)
//   [35840)  sc0  : 512 floats (exp scores row i0)
//   [37888)  redsc: 16 floats (block reductions + inv1/inv0 at [8],[9])
// ---------------------------------------------------------------------------
#define SMEM_BYTES 37952

__global__ void __launch_bounds__(256)
attn_kernel(const float* __restrict__ values,
            const float* __restrict__ Vw,
            float* __restrict__ out) {
    extern __shared__ char smem[];
    float*  vt    = (float*)smem;
    float*  red   = (float*)smem;              // aliases vt (after scores)
    float*  sc1   = (float*)(smem + 33792);
    float*  sc0   = (float*)(smem + 35840);
    float*  redsc = (float*)(smem + 37888);

    const int t = threadIdx.x;
    const int b = blockIdx.x >> 8;
    const int p = blockIdx.x & 255;
    const int i0 = p;
    const int i1 = S_ - 1 - p;

    const float* __restrict__ gQb = g_Q + b * S_ * U_;
    const float* __restrict__ gVb = g_V + b * S_ * U_;
    const float* __restrict__ valb = values + b * S_ * D_;

    const int uc = t & 15;        // u-chunk: 8 u-values
    const int jp = t >> 4;        // 0..15: j within pass

    // register-resident q1/q0/Vw chunks (loaded once, L2-resident broadcast)
    float4 q1a = ((const float4*)(gQb + i1 * U_))[uc * 2 + 0];
    float4 q1b = ((const float4*)(gQb + i1 * U_))[uc * 2 + 1];
    float4 q0a = ((const float4*)(gQb + i0 * U_))[uc * 2 + 0];
    float4 q0b = ((const float4*)(gQb + i0 * U_))[uc * 2 + 1];
    float4 wa  = ((const float4*)Vw)[uc * 2 + 0];
    float4 wb  = ((const float4*)Vw)[uc * 2 + 1];

    // ---- score phase: tiles of 64 j-columns, 4 passes of 16 j ----
    for (int jt = 0; jt <= i1; jt += 64) {
        // load v tile [64 x 128] -> vt (pad 132), float4 everywhere
        {
            const float4* src = (const float4*)(gVb + jt * U_);
            float4* dst = (float4*)vt;
            #pragma unroll
            for (int it = 0; it < 8; it++) {
                int idx4 = t + it * 256;          // 0..2047
                float4 v = src[idx4];
                int jr = idx4 >> 5;               // row (32 float4 per row)
                int u4 = idx4 & 31;
                dst[jr * 33 + u4] = v;
            }
        }
        __syncthreads();

        #pragma unroll
        for (int ps = 0; ps < 4; ps++) {
            const int j = jt + ps * 16 + jp;
            const int jwmin = j - (jp & 1);       // warp-uniform min j
            if (jwmin > i1) break;                // warp-uniform

            const float4* __restrict__ v4 =
                (const float4*)(vt + (ps * 16 + jp) * 132) + uc * 2;
            const float4 va = v4[0];
            const float4 vb = v4[1];

            // row i1
            float a1 = tanh_fast(q1a.x + va.x) * wa.x;
            a1 = fmaf(tanh_fast(q1a.y + va.y), wa.y, a1);
            a1 = fmaf(tanh_fast(q1a.z + va.z), wa.z, a1);
            a1 = fmaf(tanh_fast(q1a.w + va.w), wa.w, a1);
            a1 = fmaf(tanh_fast(q1b.x + vb.x), wb.x, a1);
            a1 = fmaf(tanh_fast(q1b.y + vb.y), wb.y, a1);
            a1 = fmaf(tanh_fast(q1b.z + vb.z), wb.z, a1);
            a1 = fmaf(tanh_fast(q1b.w + vb.w), wb.w, a1);
            #pragma unroll
            for (int o = 8; o; o >>= 1)
                a1 += __shfl_xor_sync(0xffffffffu, a1, o);
            if (uc == 0) sc1[j] = a1;

            // row i0 (warp-uniform causal skip)
            if (jwmin <= i0) {
                float a0 = tanh_fast(q0a.x + va.x) * wa.x;
                a0 = fmaf(tanh_fast(q0a.y + va.y), wa.y, a0);
                a0 = fmaf(tanh_fast(q0a.z + va.z), wa.z, a0);
                a0 = fmaf(tanh_fast(q0a.w + va.w), wa.w, a0);
                a0 = fmaf(tanh_fast(q0b.x + vb.x), wb.x, a0);
                a0 = fmaf(tanh_fast(q0b.y + vb.y), wb.y, a0);
                a0 = fmaf(tanh_fast(q0b.z + vb.z), wb.z, a0);
                a0 = fmaf(tanh_fast(q0b.w + vb.w), wb.w, a0);
                #pragma unroll
                for (int o = 8; o; o >>= 1)
                    a0 += __shfl_xor_sync(0xffffffffu, a0, o);
                if (uc == 0) sc0[j] = a0;
            }
        }
        __syncthreads();
    }

    // ---- softmax stats (exp in-place; 1/sum folded into context) ----
    {
        const bool row1 = (t < 128);
        const int  hl   = t & 127;
        float* sc = row1 ? sc1 : sc0;
        const int L = (row1 ? i1 : i0) + 1;
        const int wid = t >> 5;
        const int base = row1 ? 0 : 4;

        float m = -3.4e38f;
        for (int j = hl; j < L; j += 128) m = fmaxf(m, sc[j]);
        #pragma unroll
        for (int o = 16; o; o >>= 1) m = fmaxf(m, __shfl_xor_sync(0xffffffffu, m, o));
        if ((t & 31) == 0) redsc[wid] = m;
        __syncthreads();
        m = fmaxf(fmaxf(redsc[base], redsc[base + 1]),
                  fmaxf(redsc[base + 2], redsc[base + 3]));

        float s = 0.f;
        for (int j = hl; j < L; j += 128) {
            float e = __expf(sc[j] - m);
            sc[j] = e;
            s += e;
        }
        #pragma unroll
        for (int o = 16; o; o >>= 1) s += __shfl_xor_sync(0xffffffffu, s, o);
        __syncthreads();              // protect redsc reuse
        if ((t & 31) == 0) redsc[wid] = s;
        __syncthreads();
        s = redsc[base] + redsc[base + 1] + redsc[base + 2] + redsc[base + 3];
        if (hl == 0) redsc[8 + (row1 ? 0 : 1)] = 1.0f / s;   // inv1 @8, inv0 @9
        __syncthreads();
    }

    // ---- context: out[i] = inv * sum_j exp_j * values[b,j,:] ----
    {
        const int jg = t >> 6;            // 0..3 : j residue class
        const int dg = (t & 63) << 2;     // float4 column base
        float4 A1 = make_float4(0.f, 0.f, 0.f, 0.f);
        float4 A0 = make_float4(0.f, 0.f, 0.f, 0.f);

        #pragma unroll 2
        for (int j = jg; j <= i1; j += 4) {
            float4 v = *(const float4*)&valb[j * D_ + dg];
            float p1 = sc1[j];
            A1.x = fmaf(p1, v.x, A1.x);
            A1.y = fmaf(p1, v.y, A1.y);
            A1.z = fmaf(p1, v.z, A1.z);
            A1.w = fmaf(p1, v.w, A1.w);
            if (j <= i0) {
                float p0 = sc0[j];
                A0.x = fmaf(p0, v.x, A0.x);
                A0.y = fmaf(p0, v.y, A0.y);
                A0.z = fmaf(p0, v.z, A0.z);
                A0.w = fmaf(p0, v.w, A0.w);
            }
        }

        // partial reduction across the 4 j-classes via smem (aliases vt)
        float4* red4 = (float4*)red;
        red4[(jg * 2 + 0) * 64 + (t & 63)] = A1;
        red4[(jg * 2 + 1) * 64 + (t & 63)] = A0;
        __syncthreads();

        const bool row1 = (t < 128);
        const int  hl   = t & 127;
        const int  i    = row1 ? i1 : i0;
        const int  slot = row1 ? 0 : 1;
        const float inv = redsc[8 + slot];
        float* ob = out + (b * S_ + i) * D_;
        #pragma unroll
        for (int h = 0; h < 2; h++) {
            int d = hl + h * 128;
            float o = red[(0 * 2 + slot) * 256 + d]
                    + red[(1 * 2 + slot) * 256 + d]
                    + red[(2 * 2 + slot) * 256 + d]
                    + red[(3 * 2 + slot) * 256 + d];
            ob[d] = o * inv;
        }
    }
}

// ---------------------------------------------------------------------------
extern "C" void kernel_launch(void* const* d_in, const int* in_sizes, int n_in,
                              void* d_out, int out_size) {
    const float* values = (const float*)d_in[0];
    const float* Wq     = (const float*)d_in[1];
    const float* Wv     = (const float*)d_in[2];
    const float* Vw     = (const float*)d_in[3];
    float* out = (float*)d_out;

    cudaFuncSetAttribute(attn_kernel,
                         cudaFuncAttributeMaxDynamicSharedMemorySize, SMEM_BYTES);

    proj_kernel<<<(B_ * S_) / 8, 256>>>(values, Wq, Wv);
    attn_kernel<<<B_ * (S_ / 2), 256, SMEM_BYTES>>>(values, Vw, out);
}